// round 5
// baseline (speedup 1.0000x reference)
#include <cuda_runtime.h>

#define BATCH 32
#define NH    16
#define DK    64
#define DM    1024
#define TC    4096

#define NQ_CTA  32
#define NKV_CTA 32
#define NPROD   (NQ_CTA + NKV_CTA)

// Scratch (device globals — no allocation allowed)
__device__ float g_qp[BATCH * DM];   // scaled query projection
__device__ float g_kp[BATCH * DM];   // new-token key projection
__device__ float g_vp[BATCH * DM];   // new-token value projection
__device__ float g_x [BATCH * DM];   // attention output (pre out-proj)
__device__ int   g_q_done;           // zero-init; reset by outproj kernel
__device__ int   g_kv_done;

// ---------------------------------------------------------------------------
// Fused kernel, grid = 576 CTAs x 256 threads, all resident in one wave:
//   bid 0..31   : q-projection producers (write g_qp, bump g_q_done)
//   bid 32..63  : k/v-projection producers (write g_kp/g_vp, bump g_kv_done)
//   bid 64..575 : attention consumers, one per (b,h)
// Attention CTAs spin on g_q_done before streaming (q needed for scores) and
// on g_kv_done only at the very end (appended token) — so the k/v projection
// runs fully overlapped with the 1.07GB HBM-bound cache stream.
// ---------------------------------------------------------------------------
__global__ void __launch_bounds__(256, 4)
fused_kernel(const float* __restrict__ act,    // q input [32,1024]
             const float* __restrict__ Kc, const float* __restrict__ Vc,
             const float* __restrict__ wq, const float* __restrict__ bq,
             const float* __restrict__ wk, const float* __restrict__ bk,
             const float* __restrict__ wv, const float* __restrict__ bv)
{
    const int cta  = blockIdx.x;
    const int tid  = threadIdx.x;
    const int warp = tid >> 5;
    const int lane = tid & 31;

    if (cta < NPROD) {
        // ================= projection producer role =================
        // q: 256 warps x 4 rows = 1024 rows of wq (scale 1/8 folded in)
        // kv: 256 warps x 8 rows = 2048 rows (wk rows 0..1023, wv 1024..2047)
        const bool is_q = (cta < NQ_CTA);
        const int  gw    = (is_q ? cta : cta - NQ_CTA) * 8 + warp; // 0..255
        const int  nrows = is_q ? 4 : 8;

        for (int r = 0; r < nrows; r++) {
            int ridx = gw * nrows + r;
            const float* W; const float* bias; float* out; float scale;
            if (is_q)             { W = wq; bias = bq; out = g_qp; scale = 0.125f; }
            else if (ridx < 1024) { W = wk; bias = bk; out = g_kp; scale = 1.0f; }
            else { ridx -= 1024;    W = wv; bias = bv; out = g_vp; scale = 1.0f; }

            float4 w4[8];
#pragma unroll
            for (int c = 0; c < 8; c++)
                w4[c] = *(const float4*)(W + (size_t)ridx * DM + c * 128 + lane * 4);
            const float bval = bias[ridx];

            for (int p = 0; p < 4; p++) {        // 4 passes x 8 batches
                float acc[8];
#pragma unroll
                for (int i = 0; i < 8; i++) acc[i] = 0.0f;
#pragma unroll
                for (int c = 0; c < 8; c++) {
#pragma unroll
                    for (int bb = 0; bb < 8; bb++) {
                        float4 a4 = *(const float4*)(act + (size_t)(p * 8 + bb) * DM
                                                     + c * 128 + lane * 4);
                        acc[bb] += a4.x * w4[c].x + a4.y * w4[c].y
                                 + a4.z * w4[c].z + a4.w * w4[c].w;
                    }
                }
#pragma unroll
                for (int off = 16; off; off >>= 1)
#pragma unroll
                    for (int bb = 0; bb < 8; bb++)
                        acc[bb] += __shfl_xor_sync(0xffffffffu, acc[bb], off);
                if (lane == 0) {
#pragma unroll
                    for (int bb = 0; bb < 8; bb++)
                        out[(size_t)(p * 8 + bb) * DM + ridx] = (acc[bb] + bval) * scale;
                }
            }
        }
        __syncthreads();
        if (tid == 0) {
            __threadfence();
            atomicAdd(is_q ? &g_q_done : &g_kv_done, 1);
        }
        return;
    }

    // ================= attention consumer role =================
    const int bh   = cta - NPROD;     // 0..511
    const int b    = bh >> 4;
    const int h    = bh & 15;
    const int half = lane >> 4;       // 0 or 1
    const int li   = lane & 15;       // lane within half; dims 4*li..4*li+3

    __shared__ __align__(16) float sqf[DK];
    __shared__ float  sm[16], sl[16];
    __shared__ float4 so[16][16];
    __shared__ float  red2[2];

    // Wait for q projection (producers are wave-1 resident low-bid CTAs)
    if (tid == 0) {
        while (atomicAdd(&g_q_done, 0) < NQ_CTA) __nanosleep(200);
        __threadfence();
    }
    __syncthreads();
    if (tid < DK) sqf[tid] = g_qp[b * DM + h * DK + tid];   // pre-scaled by 1/8
    __syncthreads();

    const float4 q4 = *(const float4*)&sqf[4 * li];

    const float* Kp = Kc + (size_t)bh * TC * DK + half * DK + 4 * li;
    const float* Vp = Vc + (size_t)bh * TC * DK + half * DK + 4 * li;

    float  m = -1e30f;
    float  l = 0.0f;
    float4 o = make_float4(0.f, 0.f, 0.f, 0.f);

    // Block-softmax over 4-key blocks per half (8 keys per warp per iter).
    const int t0 = warp * (TC / 8);   // 512 keys per warp
    for (int t = t0; t < t0 + TC / 8; t += 8) {
        float4 kk[4], vv[4];
#pragma unroll
        for (int i = 0; i < 4; i++)
            kk[i] = __ldcs((const float4*)(Kp + (size_t)(t + 2 * i) * DK));
#pragma unroll
        for (int i = 0; i < 4; i++)
            vv[i] = __ldcs((const float4*)(Vp + (size_t)(t + 2 * i) * DK));

        float s[4];
#pragma unroll
        for (int i = 0; i < 4; i++)
            s[i] = kk[i].x * q4.x + kk[i].y * q4.y + kk[i].z * q4.z + kk[i].w * q4.w;
#pragma unroll
        for (int off = 8; off; off >>= 1)
#pragma unroll
            for (int i = 0; i < 4; i++)
                s[i] += __shfl_xor_sync(0xffffffffu, s[i], off);   // within half

        float bm = fmaxf(fmaxf(s[0], s[1]), fmaxf(s[2], s[3]));
        float mn = fmaxf(m, bm);

        float p[4];
#pragma unroll
        for (int i = 0; i < 4; i++) p[i] = __expf(s[i] - mn);

        float  lp = 0.0f;
        float4 op = make_float4(0.f, 0.f, 0.f, 0.f);
#pragma unroll
        for (int i = 0; i < 4; i++) {
            lp   += p[i];
            op.x += p[i] * vv[i].x;
            op.y += p[i] * vv[i].y;
            op.z += p[i] * vv[i].z;
            op.w += p[i] * vv[i].w;
        }

        float sc = __expf(m - mn);
        l   = l   * sc + lp;
        o.x = o.x * sc + op.x;
        o.y = o.y * sc + op.y;
        o.z = o.z * sc + op.z;
        o.w = o.w * sc + op.w;
        m   = mn;
    }

    // Publish 16 partial states; meanwhile wait for k/v projection (long done).
    const int idx = warp * 2 + half;
    if (li == 0) { sm[idx] = m; sl[idx] = l; }
    so[idx][li] = o;
    if (tid == 0) {
        while (atomicAdd(&g_kv_done, 0) < NKV_CTA) __nanosleep(200);
        __threadfence();
    }
    __syncthreads();

    // Merge 16 states + appended token. Threads 0..63 own one dim each.
    float prod = 0.0f, M = -1e30f, L = 0.0f, O = 0.0f, vn = 0.0f;
    if (tid < DK) {
        const int d = tid;
        M = sm[0];
#pragma unroll
        for (int i = 1; i < 16; i++) M = fmaxf(M, sm[i]);
#pragma unroll
        for (int i = 0; i < 16; i++) {
            float e = __expf(sm[i] - M);
            L += e * sl[i];
            O += e * ((const float*)so[i])[d];
        }
        float kn = g_kp[b * DM + h * DK + d];
        vn       = g_vp[b * DM + h * DK + d];
        prod = sqf[d] * kn;     // q pre-scaled -> s_new contribution
    }
#pragma unroll
    for (int off = 16; off; off >>= 1)
        prod += __shfl_xor_sync(0xffffffffu, prod, off);
    if (lane == 0 && warp < 2) red2[warp] = prod;
    __syncthreads();
    if (tid < DK) {
        float s_new = red2[0] + red2[1];
        float Mf = fmaxf(M, s_new);
        float ef = __expf(M - Mf);
        float pn = __expf(s_new - Mf);
        float Lf = L * ef + pn;
        float Of = O * ef + pn * vn;
        g_x[b * DM + h * DK + tid] = Of / Lf;
    }
}

// ---------------------------------------------------------------------------
// Output projection: out[b][j] = g_x[b]·wo[j] + bo[j].
// grid (DM/8, 1, 8), block 128. Also resets the producer counters for the
// next graph replay (stream-ordered after the fused kernel).
// ---------------------------------------------------------------------------
__global__ void outproj_kernel(const float* __restrict__ wo,
                               const float* __restrict__ bo,
                               float* __restrict__ out)
{
    if (blockIdx.x == 0 && blockIdx.z == 0 && threadIdx.x == 0) {
        g_q_done = 0;
        g_kv_done = 0;
    }

    const int warp = threadIdx.x >> 5;
    const int lane = threadIdx.x & 31;
    const int j0   = (blockIdx.x * 4 + warp) * 2;
    const int b0   = blockIdx.z * 4;

    float4 w[2][8];
#pragma unroll
    for (int r = 0; r < 2; r++) {
        const float* Wr = wo + (size_t)(j0 + r) * DM;
#pragma unroll
        for (int c = 0; c < 8; c++)
            w[r][c] = *(const float4*)(Wr + c * 128 + lane * 4);
    }

    float a[4][2];
#pragma unroll
    for (int bb = 0; bb < 4; bb++) { a[bb][0] = 0.0f; a[bb][1] = 0.0f; }

#pragma unroll
    for (int c = 0; c < 8; c++) {
#pragma unroll
        for (int bb = 0; bb < 4; bb++) {
            float4 x = *(const float4*)(g_x + (size_t)(b0 + bb) * DM + c * 128 + lane * 4);
            a[bb][0] += x.x * w[0][c].x + x.y * w[0][c].y + x.z * w[0][c].z + x.w * w[0][c].w;
            a[bb][1] += x.x * w[1][c].x + x.y * w[1][c].y + x.z * w[1][c].z + x.w * w[1][c].w;
        }
    }

#pragma unroll
    for (int off = 16; off; off >>= 1) {
#pragma unroll
        for (int bb = 0; bb < 4; bb++) {
            a[bb][0] += __shfl_xor_sync(0xffffffffu, a[bb][0], off);
            a[bb][1] += __shfl_xor_sync(0xffffffffu, a[bb][1], off);
        }
    }

    if (lane == 0) {
        const float bias0 = bo[j0], bias1 = bo[j0 + 1];
#pragma unroll
        for (int bb = 0; bb < 4; bb++) {
            out[(size_t)(b0 + bb) * DM + j0]     = a[bb][0] + bias0;
            out[(size_t)(b0 + bb) * DM + j0 + 1] = a[bb][1] + bias1;
        }
    }
}

// ---------------------------------------------------------------------------
// inputs (metadata order): 0 q, 1 key_pre, 2 value_pre,
//   3 wq, 4 bq, 5 wk, 6 bk, 7 wv, 8 bv, 9 wo, 10 bo
// output: [32, 1, 1024] fp32
// ---------------------------------------------------------------------------
extern "C" void kernel_launch(void* const* d_in, const int* in_sizes, int n_in,
                              void* d_out, int out_size)
{
    const float* q   = (const float*)d_in[0];
    const float* Kc  = (const float*)d_in[1];
    const float* Vc  = (const float*)d_in[2];
    const float* wq  = (const float*)d_in[3];
    const float* bq  = (const float*)d_in[4];
    const float* wk  = (const float*)d_in[5];
    const float* bk  = (const float*)d_in[6];
    const float* wv  = (const float*)d_in[7];
    const float* bv  = (const float*)d_in[8];
    const float* wo  = (const float*)d_in[9];
    const float* bo  = (const float*)d_in[10];
    float* out = (float*)d_out;

    fused_kernel<<<NPROD + BATCH * NH, 256>>>(q, Kc, Vc, wq, bq, wk, bk, wv, bv);
    outproj_kernel<<<dim3(DM / 8, 1, 8), 128>>>(wo, bo, out);
}